// round 6
// baseline (speedup 1.0000x reference)
#include <cuda_runtime.h>
#include <cuda_bf16.h>
#include <math.h>
#include <stdint.h>

#define BATCH 32
#define CDIM  256
#define TLEN  2048
#define NTOK  (BATCH * TLEN)   // 65536
#define KCODES 1024
#define BETA  0.25f

// ---------------- device scratch ----------------
__device__ float          g_cnorm[KCODES];
__device__ float          g_znorm[NTOK];
__device__ int            g_idx[NTOK];
__device__ unsigned int   g_counts[KCODES];
__device__ double         g_sqsum;
__device__ int            g_namb;
__device__ int            g_amb[NTOK];
__device__ __nv_bfloat16  g_zh[(size_t)NTOK * CDIM];
__device__ __nv_bfloat16  g_zl[(size_t)NTOK * CDIM];
__device__ __nv_bfloat16  g_cbh[(size_t)KCODES * CDIM];
__device__ __nv_bfloat16  g_cbl[(size_t)KCODES * CDIM];

// ---------------- PTX helpers (family-common: sm_80+ features only) ----------------
__device__ __forceinline__ uint32_t smem_u32(const void* p) {
    uint32_t a;
    asm("{ .reg .u64 t; cvta.to.shared.u64 t, %1; cvt.u32.u64 %0, t; }" : "=r"(a) : "l"(p));
    return a;
}
__device__ __forceinline__ void cp16(uint32_t dst, const void* src) {
    asm volatile("{ .reg .u64 g; cvta.to.global.u64 g, %1; cp.async.cg.shared.global [%0], [g], 16; }"
                 :: "r"(dst), "l"(src) : "memory");
}
__device__ __forceinline__ void ldsm4(uint32_t* r, uint32_t a) {
    asm volatile("ldmatrix.sync.aligned.m8n8.x4.shared.b16 {%0,%1,%2,%3}, [%4];"
                 : "=r"(r[0]), "=r"(r[1]), "=r"(r[2]), "=r"(r[3]) : "r"(a));
}
__device__ __forceinline__ void mma_bf16(float* c, const uint32_t* a, const uint32_t* b) {
    asm volatile("mma.sync.aligned.m16n8k16.row.col.f32.bf16.bf16.f32 "
                 "{%0,%1,%2,%3}, {%4,%5,%6,%7}, {%8,%9}, {%0,%1,%2,%3};"
                 : "+f"(c[0]), "+f"(c[1]), "+f"(c[2]), "+f"(c[3])
                 : "r"(a[0]), "r"(a[1]), "r"(a[2]), "r"(a[3]), "r"(b[0]), "r"(b[1]));
}

// ---------------- kernel: split codebook + cnorm + zero scalars ----------------
__global__ void vq_split_cb(const float* __restrict__ cb) {
    const int k = blockIdx.x;
    const int tid = threadIdx.x;
    float v = cb[(size_t)k * CDIM + tid];
    __nv_bfloat16 h = __float2bfloat16(v);
    float lo = v - __bfloat162float(h);
    g_cbh[(size_t)k * CDIM + tid] = h;
    g_cbl[(size_t)k * CDIM + tid] = __float2bfloat16(lo);
    __shared__ double sd[256];
    sd[tid] = (double)v * (double)v;
    __syncthreads();
    for (int o = 128; o; o >>= 1) { if (tid < o) sd[tid] += sd[tid + o]; __syncthreads(); }
    if (tid == 0) {
        g_cnorm[k] = (float)sd[0];
        g_counts[k] = 0u;
        if (k == 0) { g_sqsum = 0.0; g_namb = 0; }
    }
}

// ---------------- kernel: split z (transpose to token-major) + znorm ----------------
__global__ void vq_split_z(const float* __restrict__ z) {
    const int blk = blockIdx.x;                // NTOK/32 blocks
    const int b = blk >> 6;                    // 64 blocks per batch
    const int t0 = (blk & 63) * 32;
    const int tid = threadIdx.x;
    __shared__ float s[CDIM][33];
    __shared__ double zns[32][8];

    const float* zb = z + (size_t)b * CDIM * TLEN + t0;
    {
        int tx = tid & 31, ty = tid >> 5;
        for (int cc = ty; cc < CDIM; cc += 8)
            s[cc][tx] = zb[(size_t)cc * TLEN + tx];
    }
    __syncthreads();
    const int tl = tid >> 3;                   // token within tile
    const int q  = tid & 7;
    const int c0 = q * 32;
    const size_t n = (size_t)b * TLEN + t0 + tl;
    double ps = 0.0;
    __nv_bfloat16 hb[32], lb[32];
    #pragma unroll
    for (int j = 0; j < 32; j++) {
        float v = s[c0 + j][tl];
        __nv_bfloat16 h = __float2bfloat16(v);
        float lo = v - __bfloat162float(h);
        hb[j] = h; lb[j] = __float2bfloat16(lo);
        ps += (double)v * (double)v;
    }
    #pragma unroll
    for (int jj = 0; jj < 4; jj++) {
        *(uint4*)(g_zh + n * CDIM + c0 + jj * 8) = *(uint4*)&hb[jj * 8];
        *(uint4*)(g_zl + n * CDIM + c0 + jj * 8) = *(uint4*)&lb[jj * 8];
    }
    zns[tl][q] = ps;
    __syncthreads();
    if (q == 0) {
        double t = 0.0;
        #pragma unroll
        for (int x = 0; x < 8; x++) t += zns[tl][x];
        g_znorm[n] = (float)t;
    }
}

// ---------------- kernel: argmin GEMM via mma.sync (HMMA) ----------------
// dot via bf16-split (3 segments of K=256 => K=768), fp32 accumulators.
// d = rn(rn(zn + cn) - 2*dot), argmin with lowest-index tie-break;
// best + second-best tracked; ambiguous tokens (gap < 1e-4) rescued exactly.
#define OFF_CN 0
#define OFF_ZN 512
#define OFF_RK 1024
#define OFF_RS 3072
#define OFF_A0 4096
#define OFF_A1 (OFF_A0 + 16384)
#define OFF_B0 (OFF_A1 + 16384)
#define OFF_B1 (OFF_B0 + 16384)
#define ARGMIN_SMEM (OFF_B1 + 16384)

__global__ void __launch_bounds__(256, 2) vq_argmin_mma() {
    extern __shared__ char dsm[];
    const uint32_t base = smem_u32(dsm);
    const int tid  = threadIdx.x;
    const int lane = tid & 31;
    const int w    = tid >> 5;
    const int wm   = w & 3;          // 4 m-warps (tokens)
    const int wn   = w >> 2;         // 2 n-warps (codes)
    const int tok0 = blockIdx.x * 128;
    const int m4   = lane >> 3;      // ldmatrix sub-matrix id
    const int qrow = lane >> 2;
    const int qcol = lane & 3;

    float* sCN = (float*)(dsm + OFF_CN);
    float* sZN = (float*)(dsm + OFF_ZN);
    unsigned long long* redK = (unsigned long long*)(dsm + OFF_RK);
    float* redS = (float*)(dsm + OFF_RS);

    if (tid < 128) sZN[tid] = g_znorm[tok0 + tid];

    const __nv_bfloat16* zhp = g_zh + (size_t)tok0 * CDIM;
    const __nv_bfloat16* zlp = g_zl + (size_t)tok0 * CDIM;

    unsigned long long bkey[4];
    float secd[4];
    #pragma unroll
    for (int rr = 0; rr < 4; rr++) { bkey[rr] = 0x7F800000FFFFFFFFull; secd[rr] = 3.4e38f; }

    __syncthreads();
    float znr[4];
    #pragma unroll
    for (int rr = 0; rr < 4; rr++) {
        int row = wm * 32 + (rr >> 1) * 16 + (rr & 1) * 8 + qrow;
        znr[rr] = sZN[row];
    }

    // precompute ldmatrix row components
    const int arow_l = (m4 & 1) * 8 + (lane & 7);     // + wm*32 + mt*16
    const int brow_l = (m4 >> 1) * 8 + (lane & 7);    // + wn*64 + p2*16
    const int acolh  = (m4 >> 1) * 16;
    const int bcolh  = (m4 & 1) * 16;

    for (int kt = 0; kt < 8; kt++) {
        __syncthreads();                         // prior epilogue done with sCN
        if (tid < 128) sCN[tid] = g_cnorm[kt * 128 + tid];
        const __nv_bfloat16* bh = g_cbh + (size_t)kt * 128 * CDIM;
        const __nv_bfloat16* bl = g_cbl + (size_t)kt * 128 * CDIM;
        const __nv_bfloat16* aseg[3] = { zhp, zlp, zhp };
        const __nv_bfloat16* bseg[3] = { bh,  bh,  bl  };

        float acc[2][8][4];
        #pragma unroll
        for (int mt = 0; mt < 2; mt++)
            #pragma unroll
            for (int nt = 0; nt < 8; nt++)
                #pragma unroll
                for (int j = 0; j < 4; j++) acc[mt][nt][j] = 0.f;

        // preload chunk 0
        {
            #pragma unroll
            for (int r = 0; r < 4; r++) {
                int q = tid + r * 256;
                int row = q >> 3, c16 = q & 7;
                uint32_t dsto = (uint32_t)(row * 128 + ((c16 * 16) ^ ((row & 7) * 16)));
                cp16(base + OFF_A0 + dsto, aseg[0] + (size_t)row * CDIM + c16 * 8);
                cp16(base + OFF_B0 + dsto, bseg[0] + (size_t)row * CDIM + c16 * 8);
            }
            asm volatile("cp.async.commit_group;" ::: "memory");
        }

        for (int i = 0; i < 12; i++) {
            if (i < 11) {
                int seg = (i + 1) >> 2;
                int c0  = ((i + 1) & 3) * 64;
                uint32_t aoff = ((i + 1) & 1) ? OFF_A1 : OFF_A0;
                uint32_t boff = ((i + 1) & 1) ? OFF_B1 : OFF_B0;
                #pragma unroll
                for (int r = 0; r < 4; r++) {
                    int q = tid + r * 256;
                    int row = q >> 3, c16 = q & 7;
                    uint32_t dsto = (uint32_t)(row * 128 + ((c16 * 16) ^ ((row & 7) * 16)));
                    cp16(base + aoff + dsto, aseg[seg] + (size_t)row * CDIM + c0 + c16 * 8);
                    cp16(base + boff + dsto, bseg[seg] + (size_t)row * CDIM + c0 + c16 * 8);
                }
                asm volatile("cp.async.commit_group;" ::: "memory");
                asm volatile("cp.async.wait_group 1;" ::: "memory");
            } else {
                asm volatile("cp.async.wait_group 0;" ::: "memory");
            }
            __syncthreads();

            const uint32_t aoff = (i & 1) ? OFF_A1 : OFF_A0;
            const uint32_t boff = (i & 1) ? OFF_B1 : OFF_B0;
            #pragma unroll
            for (int k16 = 0; k16 < 4; k16++) {
                uint32_t af[2][4], bf[8][2];
                #pragma unroll
                for (int mt = 0; mt < 2; mt++) {
                    int row = wm * 32 + mt * 16 + arow_l;
                    int col = k16 * 32 + acolh;
                    ldsm4(af[mt], base + aoff +
                          (uint32_t)(row * 128 + (col ^ ((row & 7) * 16))));
                }
                #pragma unroll
                for (int p2 = 0; p2 < 4; p2++) {
                    uint32_t t4[4];
                    int row = wn * 64 + p2 * 16 + brow_l;
                    int col = k16 * 32 + bcolh;
                    ldsm4(t4, base + boff +
                          (uint32_t)(row * 128 + (col ^ ((row & 7) * 16))));
                    bf[2 * p2][0] = t4[0]; bf[2 * p2][1] = t4[1];
                    bf[2 * p2 + 1][0] = t4[2]; bf[2 * p2 + 1][1] = t4[3];
                }
                #pragma unroll
                for (int mt = 0; mt < 2; mt++)
                    #pragma unroll
                    for (int nt = 0; nt < 8; nt++)
                        mma_bf16(acc[mt][nt], af[mt], bf[nt]);
            }
            __syncthreads();
        }

        // epilogue: quantize exactly like reference, update best/second
        #pragma unroll
        for (int mt = 0; mt < 2; mt++)
            #pragma unroll
            for (int h = 0; h < 2; h++) {
                const int rr = mt * 2 + h;
                #pragma unroll
                for (int nt = 0; nt < 8; nt++)
                    #pragma unroll
                    for (int jj = 0; jj < 2; jj++) {
                        int col = wn * 64 + nt * 8 + qcol * 2 + jj;
                        float dot = acc[mt][nt][h * 2 + jj];
                        float d = __fadd_rn(__fadd_rn(znr[rr], sCN[col]),
                                            __fmul_rn(-2.0f, dot));
                        unsigned long long key =
                            ((unsigned long long)__float_as_uint(d) << 32) |
                            (unsigned)(kt * 128 + col);
                        if (key < bkey[rr]) {
                            secd[rr] = fminf(secd[rr],
                                __uint_as_float((uint32_t)(bkey[rr] >> 32)));
                            bkey[rr] = key;
                        } else {
                            secd[rr] = fminf(secd[rr], d);
                        }
                    }
            }
    }

    // quad (same-row lanes) reduction via shuffles
    #pragma unroll
    for (int rr = 0; rr < 4; rr++) {
        unsigned long long k = bkey[rr];
        float s = secd[rr];
        #pragma unroll
        for (int off = 1; off <= 2; off <<= 1) {
            unsigned long long ko = __shfl_xor_sync(0xffffffffu, k, off);
            float so = __shfl_xor_sync(0xffffffffu, s, off);
            unsigned long long kmin = (k < ko) ? k : ko;
            unsigned long long kmax = (k < ko) ? ko : k;
            s = fminf(fminf(s, so), __uint_as_float((uint32_t)(kmax >> 32)));
            k = kmin;
        }
        if (qcol == 0) {
            int row = wm * 32 + (rr >> 1) * 16 + (rr & 1) * 8 + qrow;
            redK[wn * 128 + row] = k;
            redS[wn * 128 + row] = s;
        }
    }
    __syncthreads();
    if (tid < 128) {
        unsigned long long k1 = redK[tid], k2 = redK[128 + tid];
        float s1 = redS[tid], s2 = redS[128 + tid];
        unsigned long long kb = (k1 < k2) ? k1 : k2;
        unsigned long long ko = (k1 < k2) ? k2 : k1;
        float bv = __uint_as_float((uint32_t)(kb >> 32));
        float sv = fminf(fminf(s1, s2), __uint_as_float((uint32_t)(ko >> 32)));
        int tok = tok0 + tid;
        g_idx[tok] = (int)(kb & 0xFFFFFFFFull);
        if (sv - bv < 1e-4f) {
            int p = atomicAdd(&g_namb, 1);
            g_amb[p] = tok;
        }
    }
}

// ---------------- kernel: exact fp32 rescue for ambiguous tokens ----------------
#define RG 8
#define RESCUE_SMEM ((RG * CDIM + 64 * CDIM) * 4)
__global__ void vq_rescue(const float* __restrict__ z, const float* __restrict__ cb) {
    extern __shared__ float rsm[];
    float* zs   = rsm;                 // RG x 256
    float* tile = rsm + RG * CDIM;     // 64 x 256
    __shared__ float zn_s[RG];
    __shared__ int   tok_s[RG];
    __shared__ unsigned long long bestk[RG];
    const int tid = threadIdx.x;
    const int nA = g_namb;

    for (int g0 = blockIdx.x * RG; g0 < nA; g0 += gridDim.x * RG) {
        const int ng = min(RG, nA - g0);
        if (tid < ng) {
            tok_s[tid] = g_amb[g0 + tid];
            zn_s[tid] = g_znorm[tok_s[tid]];
            bestk[tid] = 0xFFFFFFFFFFFFFFFFull;
        }
        __syncthreads();
        for (int q = tid; q < ng * CDIM; q += 256) {
            int gi = q >> 8, c = q & 255;
            int tk = tok_s[gi];
            int b = tk >> 11, t = tk & 2047;
            zs[gi * CDIM + c] = z[((size_t)b * CDIM + c) * TLEN + t];
        }
        for (int kb = 0; kb < KCODES; kb += 64) {
            __syncthreads();
            for (int q = tid; q < 64 * CDIM; q += 256)
                tile[q] = cb[(size_t)kb * CDIM + q];
            __syncthreads();
            for (int e = tid; e < 64 * ng; e += 256) {
                int kk = e & 63, gi = e >> 6;
                const float* zp = zs + gi * CDIM;
                const float* cp = tile + kk * CDIM;
                float acc = 0.f;
                #pragma unroll 8
                for (int c = 0; c < CDIM; c++)
                    acc = __fmaf_rn(zp[c], cp[c], acc);
                float d = __fadd_rn(__fadd_rn(zn_s[gi], g_cnorm[kb + kk]),
                                    __fmul_rn(-2.0f, acc));
                unsigned long long key =
                    ((unsigned long long)__float_as_uint(d) << 32) | (unsigned)(kb + kk);
                atomicMin(&bestk[gi], key);
            }
        }
        __syncthreads();
        if (tid < ng) g_idx[tok_s[tid]] = (int)(bestk[tid] & 0xFFFFFFFFull);
        __syncthreads();
    }
}

// ---------------- kernel: z_q gather + loss partial ----------------
__global__ void vq_zq_kernel(const float* __restrict__ z,
                             const float* __restrict__ cb,
                             float* __restrict__ zq_out) {
    const int b = blockIdx.x >> 8;
    const int c = blockIdx.x & 255;
    const float* zr   = z      + ((size_t)b * CDIM + c) * TLEN;
    float*       orow = zq_out + ((size_t)b * CDIM + c) * TLEN;
    const int*   idxr = g_idx + (size_t)b * TLEN;

    float s = 0.f;
    for (int t = threadIdx.x; t < TLEN; t += blockDim.x) {
        int k = idxr[t];
        float q = cb[(size_t)k * CDIM + c];
        float d = q - zr[t];
        s += d * d;
        orow[t] = q;
    }
    #pragma unroll
    for (int o = 16; o; o >>= 1) s += __shfl_down_sync(0xffffffffu, s, o);
    __shared__ float ws[8];
    if ((threadIdx.x & 31) == 0) ws[threadIdx.x >> 5] = s;
    __syncthreads();
    if (threadIdx.x == 0) {
        float tot = 0.f;
        #pragma unroll
        for (int wv = 0; wv < 8; wv++) tot += ws[wv];
        atomicAdd(&g_sqsum, (double)tot);
    }
}

// ---------------- kernel: one-hot scatter + counts + index output ----------------
__global__ void vq_scatter_kernel(float* __restrict__ onehot,
                                  float* __restrict__ idx_out) {
    int n = blockIdx.x * blockDim.x + threadIdx.x;
    if (n >= NTOK) return;
    int k = g_idx[n];
    onehot[(size_t)n * KCODES + k] = 1.0f;
    atomicAdd(&g_counts[k], 1u);
    idx_out[n] = (float)k;
}

// ---------------- kernel: finalize loss + perplexity ----------------
__global__ void vq_finalize_kernel(float* __restrict__ loss_out,
                                   float* __restrict__ perp_out) {
    const int tid = threadIdx.x;
    double local = 0.0;
    for (int k = tid; k < KCODES; k += 256) {
        float p = (float)g_counts[k] * (1.0f / (float)NTOK);
        local += (double)(p * logf(p + 1e-10f));
    }
    __shared__ double sh[256];
    sh[tid] = local;
    __syncthreads();
    for (int o = 128; o; o >>= 1) {
        if (tid < o) sh[tid] += sh[tid + o];
        __syncthreads();
    }
    if (tid == 0) {
        perp_out[0] = expf(-(float)sh[0]);
        loss_out[0] = (1.0f + BETA) *
                      (float)(g_sqsum / (double)((size_t)NTOK * CDIM));
    }
}

// ---------------- launch ----------------
extern "C" void kernel_launch(void* const* d_in, const int* in_sizes, int n_in,
                              void* d_out, int out_size) {
    const float* z  = (const float*)d_in[0];
    const float* cb = (const float*)d_in[1];
    float* out = (float*)d_out;

    const size_t n_zq = (size_t)BATCH * CDIM * TLEN;   // 16777216
    float* loss_out = out;
    float* zq_out   = out + 1;
    float* perp_out = out + 1 + n_zq;
    float* onehot   = perp_out + 1;
    float* idx_out  = onehot + (size_t)NTOK * KCODES;

    cudaFuncSetAttribute(vq_argmin_mma, cudaFuncAttributeMaxDynamicSharedMemorySize, ARGMIN_SMEM);
    cudaFuncSetAttribute(vq_rescue,     cudaFuncAttributeMaxDynamicSharedMemorySize, RESCUE_SMEM);

    cudaMemsetAsync(onehot, 0, (size_t)NTOK * KCODES * sizeof(float), 0);

    vq_split_cb<<<KCODES, 256>>>(cb);
    vq_split_z<<<NTOK / 32, 256>>>(z);
    vq_argmin_mma<<<NTOK / 128, 256, ARGMIN_SMEM>>>();
    vq_rescue<<<128, 256, RESCUE_SMEM>>>(z, cb);
    vq_zq_kernel<<<BATCH * CDIM, 256>>>(z, cb, zq_out);
    vq_scatter_kernel<<<NTOK / 256, 256>>>(onehot, idx_out);
    vq_finalize_kernel<<<1, 256>>>(loss_out, perp_out);
}

// round 10
// speedup vs baseline: 1.2496x; 1.2496x over previous
#include <cuda_runtime.h>
#include <cuda_bf16.h>
#include <math.h>
#include <stdint.h>

#define BATCH 32
#define CDIM  256
#define TLEN  2048
#define NTOK  (BATCH * TLEN)   // 65536
#define KCODES 1024
#define BETA  0.25f

// ---------------- device scratch ----------------
__device__ float          g_cnorm[KCODES];
__device__ float          g_znorm[NTOK];
__device__ int            g_idx[NTOK];
__device__ unsigned int   g_counts[KCODES];
__device__ double         g_sqsum;
__device__ int            g_namb;
__device__ int            g_amb[NTOK];
__device__ __nv_bfloat16  g_zh[(size_t)NTOK * CDIM];
__device__ __nv_bfloat16  g_zl[(size_t)NTOK * CDIM];
__device__ __nv_bfloat16  g_cbh[(size_t)KCODES * CDIM];
__device__ __nv_bfloat16  g_cbl[(size_t)KCODES * CDIM];

// ---------------- PTX helpers (family-common: sm_80+ features only) ----------------
__device__ __forceinline__ uint32_t smem_u32(const void* p) {
    uint32_t a;
    asm("{ .reg .u64 t; cvta.to.shared.u64 t, %1; cvt.u32.u64 %0, t; }" : "=r"(a) : "l"(p));
    return a;
}
__device__ __forceinline__ void cp16(uint32_t dst, const void* src) {
    asm volatile("{ .reg .u64 g; cvta.to.global.u64 g, %1; cp.async.cg.shared.global [%0], [g], 16; }"
                 :: "r"(dst), "l"(src) : "memory");
}
__device__ __forceinline__ void ldsm4(uint32_t* r, uint32_t a) {
    asm volatile("ldmatrix.sync.aligned.m8n8.x4.shared.b16 {%0,%1,%2,%3}, [%4];"
                 : "=r"(r[0]), "=r"(r[1]), "=r"(r[2]), "=r"(r[3]) : "r"(a));
}
__device__ __forceinline__ void mma_bf16(float* c, const uint32_t* a, const uint32_t* b) {
    asm volatile("mma.sync.aligned.m16n8k16.row.col.f32.bf16.bf16.f32 "
                 "{%0,%1,%2,%3}, {%4,%5,%6,%7}, {%8,%9}, {%0,%1,%2,%3};"
                 : "+f"(c[0]), "+f"(c[1]), "+f"(c[2]), "+f"(c[3])
                 : "r"(a[0]), "r"(a[1]), "r"(a[2]), "r"(a[3]), "r"(b[0]), "r"(b[1]));
}

// ---------------- kernel: split codebook + cnorm + zero scalars ----------------
__global__ void vq_split_cb(const float* __restrict__ cb) {
    const int k = blockIdx.x;
    const int tid = threadIdx.x;
    float v = cb[(size_t)k * CDIM + tid];
    __nv_bfloat16 h = __float2bfloat16(v);
    float lo = v - __bfloat162float(h);
    g_cbh[(size_t)k * CDIM + tid] = h;
    g_cbl[(size_t)k * CDIM + tid] = __float2bfloat16(lo);
    __shared__ double sd[256];
    sd[tid] = (double)v * (double)v;
    __syncthreads();
    for (int o = 128; o; o >>= 1) { if (tid < o) sd[tid] += sd[tid + o]; __syncthreads(); }
    if (tid == 0) {
        g_cnorm[k] = (float)sd[0];
        g_counts[k] = 0u;
        if (k == 0) { g_sqsum = 0.0; g_namb = 0; }
    }
}

// ---------------- kernel: split z (transpose to token-major) + znorm ----------------
__global__ void vq_split_z(const float* __restrict__ z) {
    const int blk = blockIdx.x;                // NTOK/32 blocks
    const int b = blk >> 6;                    // 64 blocks per batch
    const int t0 = (blk & 63) * 32;
    const int tid = threadIdx.x;
    __shared__ float s[CDIM][33];
    __shared__ double zns[32][8];

    const float* zb = z + (size_t)b * CDIM * TLEN + t0;
    {
        int tx = tid & 31, ty = tid >> 5;
        for (int cc = ty; cc < CDIM; cc += 8)
            s[cc][tx] = zb[(size_t)cc * TLEN + tx];
    }
    __syncthreads();
    const int tl = tid >> 3;                   // token within tile
    const int q  = tid & 7;
    const int c0 = q * 32;
    const size_t n = (size_t)b * TLEN + t0 + tl;
    double ps = 0.0;
    __nv_bfloat16 hb[32], lb[32];
    #pragma unroll
    for (int j = 0; j < 32; j++) {
        float v = s[c0 + j][tl];
        __nv_bfloat16 h = __float2bfloat16(v);
        float lo = v - __bfloat162float(h);
        hb[j] = h; lb[j] = __float2bfloat16(lo);
        ps += (double)v * (double)v;
    }
    #pragma unroll
    for (int jj = 0; jj < 4; jj++) {
        *(uint4*)(g_zh + n * CDIM + c0 + jj * 8) = *(uint4*)&hb[jj * 8];
        *(uint4*)(g_zl + n * CDIM + c0 + jj * 8) = *(uint4*)&lb[jj * 8];
    }
    zns[tl][q] = ps;
    __syncthreads();
    if (q == 0) {
        double t = 0.0;
        #pragma unroll
        for (int x = 0; x < 8; x++) t += zns[tl][x];
        g_znorm[n] = (float)t;
    }
}

// ---------------- kernel: argmin GEMM via mma.sync (HMMA) ----------------
// dot via bf16-split (3 segments of K=256 => K=768), fp32 accumulators.
// d = rn(rn(zn + cn) - 2*dot), argmin with lowest-index tie-break;
// best + second-best tracked; tokens with quantized gap <= 2 ulp rescued exactly.
#define OFF_CN 0
#define OFF_ZN 512
#define OFF_RK 1024
#define OFF_RS 3072
#define OFF_A0 4096
#define OFF_A1 (OFF_A0 + 16384)
#define OFF_B0 (OFF_A1 + 16384)
#define OFF_B1 (OFF_B0 + 16384)
#define ARGMIN_SMEM (OFF_B1 + 16384)

__global__ void __launch_bounds__(256, 2) vq_argmin_mma() {
    extern __shared__ char dsm[];
    const uint32_t base = smem_u32(dsm);
    const int tid  = threadIdx.x;
    const int lane = tid & 31;
    const int w    = tid >> 5;
    const int wm   = w & 3;          // 4 m-warps (tokens)
    const int wn   = w >> 2;         // 2 n-warps (codes)
    const int tok0 = blockIdx.x * 128;
    const int m4   = lane >> 3;      // ldmatrix sub-matrix id
    const int qrow = lane >> 2;
    const int qcol = lane & 3;

    float* sCN = (float*)(dsm + OFF_CN);
    float* sZN = (float*)(dsm + OFF_ZN);
    unsigned long long* redK = (unsigned long long*)(dsm + OFF_RK);
    float* redS = (float*)(dsm + OFF_RS);

    if (tid < 128) sZN[tid] = g_znorm[tok0 + tid];

    const __nv_bfloat16* zhp = g_zh + (size_t)tok0 * CDIM;
    const __nv_bfloat16* zlp = g_zl + (size_t)tok0 * CDIM;

    unsigned long long bkey[4];
    float secd[4];
    #pragma unroll
    for (int rr = 0; rr < 4; rr++) { bkey[rr] = 0x7F800000FFFFFFFFull; secd[rr] = 3.4e38f; }

    __syncthreads();
    float znr[4];
    #pragma unroll
    for (int rr = 0; rr < 4; rr++) {
        int row = wm * 32 + (rr >> 1) * 16 + (rr & 1) * 8 + qrow;
        znr[rr] = sZN[row];
    }

    // precompute ldmatrix row components
    const int arow_l = (m4 & 1) * 8 + (lane & 7);     // + wm*32 + mt*16
    const int brow_l = (m4 >> 1) * 8 + (lane & 7);    // + wn*64 + p2*16
    const int acolh  = (m4 >> 1) * 16;                // byte offset
    const int bcolh  = (m4 & 1) * 16;                 // byte offset

    for (int kt = 0; kt < 8; kt++) {
        __syncthreads();                         // prior epilogue done with sCN
        if (tid < 128) sCN[tid] = g_cnorm[kt * 128 + tid];
        const __nv_bfloat16* bh = g_cbh + (size_t)kt * 128 * CDIM;
        const __nv_bfloat16* bl = g_cbl + (size_t)kt * 128 * CDIM;
        const __nv_bfloat16* aseg[3] = { zhp, zlp, zhp };
        const __nv_bfloat16* bseg[3] = { bh,  bh,  bl  };

        float acc[2][8][4];
        #pragma unroll
        for (int mt = 0; mt < 2; mt++)
            #pragma unroll
            for (int nt = 0; nt < 8; nt++)
                #pragma unroll
                for (int j = 0; j < 4; j++) acc[mt][nt][j] = 0.f;

        // preload chunk 0
        {
            #pragma unroll
            for (int r = 0; r < 4; r++) {
                int q = tid + r * 256;
                int row = q >> 3, c16 = q & 7;
                uint32_t dsto = (uint32_t)(row * 128 + ((c16 * 16) ^ ((row & 7) * 16)));
                cp16(base + OFF_A0 + dsto, aseg[0] + (size_t)row * CDIM + c16 * 8);
                cp16(base + OFF_B0 + dsto, bseg[0] + (size_t)row * CDIM + c16 * 8);
            }
            asm volatile("cp.async.commit_group;" ::: "memory");
        }

        for (int i = 0; i < 12; i++) {
            if (i < 11) {
                int seg = (i + 1) >> 2;
                int c0  = ((i + 1) & 3) * 64;
                uint32_t aoff = ((i + 1) & 1) ? OFF_A1 : OFF_A0;
                uint32_t boff = ((i + 1) & 1) ? OFF_B1 : OFF_B0;
                #pragma unroll
                for (int r = 0; r < 4; r++) {
                    int q = tid + r * 256;
                    int row = q >> 3, c16 = q & 7;
                    uint32_t dsto = (uint32_t)(row * 128 + ((c16 * 16) ^ ((row & 7) * 16)));
                    cp16(base + aoff + dsto, aseg[seg] + (size_t)row * CDIM + c0 + c16 * 8);
                    cp16(base + boff + dsto, bseg[seg] + (size_t)row * CDIM + c0 + c16 * 8);
                }
                asm volatile("cp.async.commit_group;" ::: "memory");
                asm volatile("cp.async.wait_group 1;" ::: "memory");
            } else {
                asm volatile("cp.async.wait_group 0;" ::: "memory");
            }
            __syncthreads();

            const uint32_t aoff = (i & 1) ? OFF_A1 : OFF_A0;
            const uint32_t boff = (i & 1) ? OFF_B1 : OFF_B0;
            #pragma unroll
            for (int k16 = 0; k16 < 4; k16++) {
                uint32_t af[2][4], bf[8][2];
                #pragma unroll
                for (int mt = 0; mt < 2; mt++) {
                    int row = wm * 32 + mt * 16 + arow_l;
                    int col = k16 * 32 + acolh;
                    ldsm4(af[mt], base + aoff +
                          (uint32_t)(row * 128 + (col ^ ((row & 7) * 16))));
                }
                #pragma unroll
                for (int p2 = 0; p2 < 4; p2++) {
                    uint32_t t4[4];
                    int row = wn * 64 + p2 * 16 + brow_l;
                    int col = k16 * 32 + bcolh;
                    ldsm4(t4, base + boff +
                          (uint32_t)(row * 128 + (col ^ ((row & 7) * 16))));
                    bf[2 * p2][0] = t4[0]; bf[2 * p2][1] = t4[1];
                    bf[2 * p2 + 1][0] = t4[2]; bf[2 * p2 + 1][1] = t4[3];
                }
                #pragma unroll
                for (int mt = 0; mt < 2; mt++)
                    #pragma unroll
                    for (int nt = 0; nt < 8; nt++)
                        mma_bf16(acc[mt][nt], af[mt], bf[nt]);
            }
            __syncthreads();
        }

        // epilogue: quantize exactly like reference, update best/second
        #pragma unroll
        for (int mt = 0; mt < 2; mt++)
            #pragma unroll
            for (int h = 0; h < 2; h++) {
                const int rr = mt * 2 + h;
                #pragma unroll
                for (int nt = 0; nt < 8; nt++)
                    #pragma unroll
                    for (int jj = 0; jj < 2; jj++) {
                        int col = wn * 64 + nt * 8 + qcol * 2 + jj;
                        float dot = acc[mt][nt][h * 2 + jj];
                        float d = __fadd_rn(__fadd_rn(znr[rr], sCN[col]),
                                            __fmul_rn(-2.0f, dot));
                        unsigned long long key =
                            ((unsigned long long)__float_as_uint(d) << 32) |
                            (unsigned)(kt * 128 + col);
                        if (key < bkey[rr]) {
                            secd[rr] = fminf(secd[rr],
                                __uint_as_float((uint32_t)(bkey[rr] >> 32)));
                            bkey[rr] = key;
                        } else {
                            secd[rr] = fminf(secd[rr], d);
                        }
                    }
            }
    }

    // quad (same-row lanes) reduction via shuffles
    #pragma unroll
    for (int rr = 0; rr < 4; rr++) {
        unsigned long long k = bkey[rr];
        float s = secd[rr];
        #pragma unroll
        for (int off = 1; off <= 2; off <<= 1) {
            unsigned long long ko = __shfl_xor_sync(0xffffffffu, k, off);
            float so = __shfl_xor_sync(0xffffffffu, s, off);
            unsigned long long kmin = (k < ko) ? k : ko;
            unsigned long long kmax = (k < ko) ? ko : k;
            s = fminf(fminf(s, so), __uint_as_float((uint32_t)(kmax >> 32)));
            k = kmin;
        }
        if (qcol == 0) {
            int row = wm * 32 + (rr >> 1) * 16 + (rr & 1) * 8 + qrow;
            redK[wn * 128 + row] = k;
            redS[wn * 128 + row] = s;
        }
    }
    __syncthreads();
    if (tid < 128) {
        unsigned long long k1 = redK[tid], k2 = redK[128 + tid];
        float s1 = redS[tid], s2 = redS[128 + tid];
        unsigned long long kb = (k1 < k2) ? k1 : k2;
        unsigned long long ko = (k1 < k2) ? k2 : k1;
        float bv = __uint_as_float((uint32_t)(kb >> 32));
        float sv = fminf(fminf(s1, s2), __uint_as_float((uint32_t)(ko >> 32)));
        int tok = tok0 + tid;
        g_idx[tok] = (int)(kb & 0xFFFFFFFFull);
        // flag only gap <= 2 ulp of the [256,512) binade (6.1e-5); >= 3 ulp is
        // provably decided identically to the reference (dot error << ulp/2).
        if (sv - bv < 6.2e-5f) {
            int p = atomicAdd(&g_namb, 1);
            g_amb[p] = tok;
        }
    }
}

// ---------------- kernel: exact fp32 rescue for ambiguous tokens ----------------
// 32 tokens per block (lane = token). z stored transposed zsT[c][tok] so each
// z chunk is loaded once into registers and reused across 8 code-chains per
// warp (ILP-8 independent sequential FMA chains -> issue-bound).
#define RG2 32
#define RESCUE_SMEM ((64 * CDIM + CDIM * RG2) * 4)   // 64KB tile + 32KB zsT
__global__ void __launch_bounds__(256, 2)
vq_rescue(const float* __restrict__ z, const float* __restrict__ cb) {
    extern __shared__ float rs[];
    float* tile = rs;                  // [64][256]
    float* zsT  = rs + 64 * CDIM;      // [256][32]
    __shared__ float zn_s[RG2];
    __shared__ int   tok_s[RG2];
    __shared__ unsigned long long bestk[RG2];
    const int tid = threadIdx.x;
    const int lane = tid & 31;
    const int w = tid >> 5;
    const int nA = g_namb;

    for (int g0 = blockIdx.x * RG2; g0 < nA; g0 += gridDim.x * RG2) {
        const int ng = min(RG2, nA - g0);
        __syncthreads();
        if (tid < ng) {
            tok_s[tid] = g_amb[g0 + tid];
            zn_s[tid] = g_znorm[tok_s[tid]];
            bestk[tid] = 0xFFFFFFFFFFFFFFFFull;
        }
        __syncthreads();
        for (int q = tid; q < CDIM * RG2; q += 256) {
            int c = q >> 5, tl = q & 31;
            if (tl < ng) {
                int tk = tok_s[tl];
                int b = tk >> 11, t = tk & 2047;
                zsT[c * RG2 + tl] = z[((size_t)b * CDIM + c) * TLEN + t];
            }
        }
        for (int kb = 0; kb < KCODES; kb += 64) {
            __syncthreads();
            {
                const float4* src = (const float4*)(cb + (size_t)kb * CDIM);
                float4* dst = (float4*)tile;
                for (int q = tid; q < 64 * CDIM / 4; q += 256)
                    dst[q] = src[q];
            }
            __syncthreads();
            if (lane < ng) {
                float acc[8];
                #pragma unroll
                for (int j = 0; j < 8; j++) acc[j] = 0.f;
                const int cj0 = w * 8;
                for (int c0 = 0; c0 < CDIM; c0 += 8) {
                    float zreg[8];
                    #pragma unroll
                    for (int cc = 0; cc < 8; cc++)
                        zreg[cc] = zsT[(c0 + cc) * RG2 + lane];
                    #pragma unroll
                    for (int j = 0; j < 8; j++) {
                        const float* cp = tile + (cj0 + j) * CDIM + c0;
                        #pragma unroll
                        for (int cc = 0; cc < 8; cc++)
                            acc[j] = __fmaf_rn(zreg[cc], cp[cc], acc[j]);
                    }
                }
                unsigned long long kmin = 0xFFFFFFFFFFFFFFFFull;
                #pragma unroll
                for (int j = 0; j < 8; j++) {
                    int kk = kb + cj0 + j;
                    float d = __fadd_rn(__fadd_rn(zn_s[lane], g_cnorm[kk]),
                                        __fmul_rn(-2.0f, acc[j]));
                    unsigned long long key =
                        ((unsigned long long)__float_as_uint(d) << 32) | (unsigned)kk;
                    if (key < kmin) kmin = key;
                }
                atomicMin(&bestk[lane], kmin);
            }
        }
        __syncthreads();
        if (tid < ng) g_idx[tok_s[tid]] = (int)(bestk[tid] & 0xFFFFFFFFull);
    }
}

// ---------------- kernel: z_q gather + loss partial ----------------
__global__ void vq_zq_kernel(const float* __restrict__ z,
                             const float* __restrict__ cb,
                             float* __restrict__ zq_out) {
    const int b = blockIdx.x >> 8;
    const int c = blockIdx.x & 255;
    const float* zr   = z      + ((size_t)b * CDIM + c) * TLEN;
    float*       orow = zq_out + ((size_t)b * CDIM + c) * TLEN;
    const int*   idxr = g_idx + (size_t)b * TLEN;

    float s = 0.f;
    for (int t = threadIdx.x; t < TLEN; t += blockDim.x) {
        int k = idxr[t];
        float q = cb[(size_t)k * CDIM + c];
        float d = q - zr[t];
        s += d * d;
        orow[t] = q;
    }
    #pragma unroll
    for (int o = 16; o; o >>= 1) s += __shfl_down_sync(0xffffffffu, s, o);
    __shared__ float ws[8];
    if ((threadIdx.x & 31) == 0) ws[threadIdx.x >> 5] = s;
    __syncthreads();
    if (threadIdx.x == 0) {
        float tot = 0.f;
        #pragma unroll
        for (int wv = 0; wv < 8; wv++) tot += ws[wv];
        atomicAdd(&g_sqsum, (double)tot);
    }
}

// ---------------- kernel: one-hot scatter + counts + index output ----------------
__global__ void vq_scatter_kernel(float* __restrict__ onehot,
                                  float* __restrict__ idx_out) {
    int n = blockIdx.x * blockDim.x + threadIdx.x;
    if (n >= NTOK) return;
    int k = g_idx[n];
    onehot[(size_t)n * KCODES + k] = 1.0f;
    atomicAdd(&g_counts[k], 1u);
    idx_out[n] = (float)k;
}

// ---------------- kernel: finalize loss + perplexity ----------------
__global__ void vq_finalize_kernel(float* __restrict__ loss_out,
                                   float* __restrict__ perp_out) {
    const int tid = threadIdx.x;
    double local = 0.0;
    for (int k = tid; k < KCODES; k += 256) {
        float p = (float)g_counts[k] * (1.0f / (float)NTOK);
        local += (double)(p * logf(p + 1e-10f));
    }
    __shared__ double sh[256];
    sh[tid] = local;
    __syncthreads();
    for (int o = 128; o; o >>= 1) {
        if (tid < o) sh[tid] += sh[tid + o];
        __syncthreads();
    }
    if (tid == 0) {
        perp_out[0] = expf(-(float)sh[0]);
        loss_out[0] = (1.0f + BETA) *
                      (float)(g_sqsum / (double)((size_t)NTOK * CDIM));
    }
}

// ---------------- launch ----------------
extern "C" void kernel_launch(void* const* d_in, const int* in_sizes, int n_in,
                              void* d_out, int out_size) {
    const float* z  = (const float*)d_in[0];
    const float* cb = (const float*)d_in[1];
    float* out = (float*)d_out;

    const size_t n_zq = (size_t)BATCH * CDIM * TLEN;   // 16777216
    float* loss_out = out;
    float* zq_out   = out + 1;
    float* perp_out = out + 1 + n_zq;
    float* onehot   = perp_out + 1;
    float* idx_out  = onehot + (size_t)NTOK * KCODES;

    cudaFuncSetAttribute(vq_argmin_mma, cudaFuncAttributeMaxDynamicSharedMemorySize, ARGMIN_SMEM);
    cudaFuncSetAttribute(vq_rescue,     cudaFuncAttributeMaxDynamicSharedMemorySize, RESCUE_SMEM);

    cudaMemsetAsync(onehot, 0, (size_t)NTOK * KCODES * sizeof(float), 0);

    vq_split_cb<<<KCODES, 256>>>(cb);
    vq_split_z<<<NTOK / 32, 256>>>(z);
    vq_argmin_mma<<<NTOK / 128, 256, ARGMIN_SMEM>>>();
    vq_rescue<<<2048, 256, RESCUE_SMEM>>>(z, cb);
    vq_zq_kernel<<<BATCH * CDIM, 256>>>(z, cb, zq_out);
    vq_scatter_kernel<<<NTOK / 256, 256>>>(onehot, idx_out);
    vq_finalize_kernel<<<1, 256>>>(loss_out, perp_out);
}

// round 12
// speedup vs baseline: 2.2489x; 1.7997x over previous
#include <cuda_runtime.h>
#include <cuda_bf16.h>
#include <math.h>
#include <stdint.h>

#define BATCH 32
#define CDIM  256
#define TLEN  2048
#define NTOK  (BATCH * TLEN)   // 65536
#define KCODES 1024
#define BETA  0.25f

// ---------------- device scratch ----------------
__device__ float          g_cnorm[KCODES];
__device__ float          g_znorm[NTOK];
__device__ int            g_idx[NTOK];
__device__ unsigned int   g_counts[KCODES];
__device__ double         g_sqsum;
__device__ int            g_namb;
__device__ int            g_amb[NTOK];
__device__ unsigned long long g_bkey[NTOK];
__device__ __nv_bfloat16  g_zh[(size_t)NTOK * CDIM];
__device__ __nv_bfloat16  g_zl[(size_t)NTOK * CDIM];
__device__ __nv_bfloat16  g_cbh[(size_t)KCODES * CDIM];
__device__ __nv_bfloat16  g_cbl[(size_t)KCODES * CDIM];

// ---------------- PTX helpers (family-common: sm_80+ features only) ----------------
__device__ __forceinline__ uint32_t smem_u32(const void* p) {
    uint32_t a;
    asm("{ .reg .u64 t; cvta.to.shared.u64 t, %1; cvt.u32.u64 %0, t; }" : "=r"(a) : "l"(p));
    return a;
}
__device__ __forceinline__ void cp16(uint32_t dst, const void* src) {
    asm volatile("{ .reg .u64 g; cvta.to.global.u64 g, %1; cp.async.cg.shared.global [%0], [g], 16; }"
                 :: "r"(dst), "l"(src) : "memory");
}
__device__ __forceinline__ void ldsm4(uint32_t* r, uint32_t a) {
    asm volatile("ldmatrix.sync.aligned.m8n8.x4.shared.b16 {%0,%1,%2,%3}, [%4];"
                 : "=r"(r[0]), "=r"(r[1]), "=r"(r[2]), "=r"(r[3]) : "r"(a));
}
__device__ __forceinline__ void mma_bf16(float* c, const uint32_t* a, const uint32_t* b) {
    asm volatile("mma.sync.aligned.m16n8k16.row.col.f32.bf16.bf16.f32 "
                 "{%0,%1,%2,%3}, {%4,%5,%6,%7}, {%8,%9}, {%0,%1,%2,%3};"
                 : "+f"(c[0]), "+f"(c[1]), "+f"(c[2]), "+f"(c[3])
                 : "r"(a[0]), "r"(a[1]), "r"(a[2]), "r"(a[3]), "r"(b[0]), "r"(b[1]));
}

// ---------------- kernel: split codebook + cnorm + zero scalars ----------------
__global__ void vq_split_cb(const float* __restrict__ cb) {
    const int k = blockIdx.x;
    const int tid = threadIdx.x;
    float v = cb[(size_t)k * CDIM + tid];
    __nv_bfloat16 h = __float2bfloat16(v);
    float lo = v - __bfloat162float(h);
    g_cbh[(size_t)k * CDIM + tid] = h;
    g_cbl[(size_t)k * CDIM + tid] = __float2bfloat16(lo);
    __shared__ double sd[256];
    sd[tid] = (double)v * (double)v;
    __syncthreads();
    for (int o = 128; o; o >>= 1) { if (tid < o) sd[tid] += sd[tid + o]; __syncthreads(); }
    if (tid == 0) {
        g_cnorm[k] = (float)sd[0];
        g_counts[k] = 0u;
        if (k == 0) { g_sqsum = 0.0; g_namb = 0; }
    }
}

// ---------------- kernel: split z (transpose to token-major) + znorm ----------------
__global__ void vq_split_z(const float* __restrict__ z) {
    const int blk = blockIdx.x;                // NTOK/32 blocks
    const int b = blk >> 6;                    // 64 blocks per batch
    const int t0 = (blk & 63) * 32;
    const int tid = threadIdx.x;
    __shared__ float s[CDIM][33];
    __shared__ double zns[32][8];

    const float* zb = z + (size_t)b * CDIM * TLEN + t0;
    {
        int tx = tid & 31, ty = tid >> 5;
        for (int cc = ty; cc < CDIM; cc += 8)
            s[cc][tx] = zb[(size_t)cc * TLEN + tx];
    }
    __syncthreads();
    const int tl = tid >> 3;                   // token within tile
    const int q  = tid & 7;
    const int c0 = q * 32;
    const size_t n = (size_t)b * TLEN + t0 + tl;
    double ps = 0.0;
    __nv_bfloat16 hb[32], lb[32];
    #pragma unroll
    for (int j = 0; j < 32; j++) {
        float v = s[c0 + j][tl];
        __nv_bfloat16 h = __float2bfloat16(v);
        float lo = v - __bfloat162float(h);
        hb[j] = h; lb[j] = __float2bfloat16(lo);
        ps += (double)v * (double)v;
    }
    #pragma unroll
    for (int jj = 0; jj < 4; jj++) {
        *(uint4*)(g_zh + n * CDIM + c0 + jj * 8) = *(uint4*)&hb[jj * 8];
        *(uint4*)(g_zl + n * CDIM + c0 + jj * 8) = *(uint4*)&lb[jj * 8];
    }
    zns[tl][q] = ps;
    __syncthreads();
    if (q == 0) {
        double t = 0.0;
        #pragma unroll
        for (int x = 0; x < 8; x++) t += zns[tl][x];
        g_znorm[n] = (float)t;
    }
}

// ---------------- kernel: argmin GEMM via mma.sync (HMMA) ----------------
// dot via bf16-split (3 segments of K=256 => K=768), fp32 accumulators.
// d = rn(rn(zn + cn) - 2*dot), argmin with lowest-index tie-break;
// best + second-best tracked; tokens with quantized gap <= 2 ulp rescued exactly.
#define OFF_CN 0
#define OFF_ZN 512
#define OFF_RK 1024
#define OFF_RS 3072
#define OFF_A0 4096
#define OFF_A1 (OFF_A0 + 16384)
#define OFF_B0 (OFF_A1 + 16384)
#define OFF_B1 (OFF_B0 + 16384)
#define ARGMIN_SMEM (OFF_B1 + 16384)

__global__ void __launch_bounds__(256, 2) vq_argmin_mma() {
    extern __shared__ char dsm[];
    const uint32_t base = smem_u32(dsm);
    const int tid  = threadIdx.x;
    const int lane = tid & 31;
    const int w    = tid >> 5;
    const int wm   = w & 3;          // 4 m-warps (tokens)
    const int wn   = w >> 2;         // 2 n-warps (codes)
    const int tok0 = blockIdx.x * 128;
    const int m4   = lane >> 3;      // ldmatrix sub-matrix id
    const int qrow = lane >> 2;
    const int qcol = lane & 3;

    float* sCN = (float*)(dsm + OFF_CN);
    float* sZN = (float*)(dsm + OFF_ZN);
    unsigned long long* redK = (unsigned long long*)(dsm + OFF_RK);
    float* redS = (float*)(dsm + OFF_RS);

    if (tid < 128) sZN[tid] = g_znorm[tok0 + tid];

    const __nv_bfloat16* zhp = g_zh + (size_t)tok0 * CDIM;
    const __nv_bfloat16* zlp = g_zl + (size_t)tok0 * CDIM;

    unsigned long long bkey[4];
    float secd[4];
    #pragma unroll
    for (int rr = 0; rr < 4; rr++) { bkey[rr] = 0x7F800000FFFFFFFFull; secd[rr] = 3.4e38f; }

    __syncthreads();
    float znr[4];
    #pragma unroll
    for (int rr = 0; rr < 4; rr++) {
        int row = wm * 32 + (rr >> 1) * 16 + (rr & 1) * 8 + qrow;
        znr[rr] = sZN[row];
    }

    // precompute ldmatrix row components
    const int arow_l = (m4 & 1) * 8 + (lane & 7);     // + wm*32 + mt*16
    const int brow_l = (m4 >> 1) * 8 + (lane & 7);    // + wn*64 + p2*16
    const int acolh  = (m4 >> 1) * 16;                // byte offset
    const int bcolh  = (m4 & 1) * 16;                 // byte offset

    for (int kt = 0; kt < 8; kt++) {
        __syncthreads();                         // prior epilogue done with sCN
        if (tid < 128) sCN[tid] = g_cnorm[kt * 128 + tid];
        const __nv_bfloat16* bh = g_cbh + (size_t)kt * 128 * CDIM;
        const __nv_bfloat16* bl = g_cbl + (size_t)kt * 128 * CDIM;
        const __nv_bfloat16* aseg[3] = { zhp, zlp, zhp };
        const __nv_bfloat16* bseg[3] = { bh,  bh,  bl  };

        float acc[2][8][4];
        #pragma unroll
        for (int mt = 0; mt < 2; mt++)
            #pragma unroll
            for (int nt = 0; nt < 8; nt++)
                #pragma unroll
                for (int j = 0; j < 4; j++) acc[mt][nt][j] = 0.f;

        // preload chunk 0
        {
            #pragma unroll
            for (int r = 0; r < 4; r++) {
                int q = tid + r * 256;
                int row = q >> 3, c16 = q & 7;
                uint32_t dsto = (uint32_t)(row * 128 + ((c16 * 16) ^ ((row & 7) * 16)));
                cp16(base + OFF_A0 + dsto, aseg[0] + (size_t)row * CDIM + c16 * 8);
                cp16(base + OFF_B0 + dsto, bseg[0] + (size_t)row * CDIM + c16 * 8);
            }
            asm volatile("cp.async.commit_group;" ::: "memory");
        }

        for (int i = 0; i < 12; i++) {
            if (i < 11) {
                int seg = (i + 1) >> 2;
                int c0  = ((i + 1) & 3) * 64;
                uint32_t aoff = ((i + 1) & 1) ? OFF_A1 : OFF_A0;
                uint32_t boff = ((i + 1) & 1) ? OFF_B1 : OFF_B0;
                #pragma unroll
                for (int r = 0; r < 4; r++) {
                    int q = tid + r * 256;
                    int row = q >> 3, c16 = q & 7;
                    uint32_t dsto = (uint32_t)(row * 128 + ((c16 * 16) ^ ((row & 7) * 16)));
                    cp16(base + aoff + dsto, aseg[seg] + (size_t)row * CDIM + c0 + c16 * 8);
                    cp16(base + boff + dsto, bseg[seg] + (size_t)row * CDIM + c0 + c16 * 8);
                }
                asm volatile("cp.async.commit_group;" ::: "memory");
                asm volatile("cp.async.wait_group 1;" ::: "memory");
            } else {
                asm volatile("cp.async.wait_group 0;" ::: "memory");
            }
            __syncthreads();

            const uint32_t aoff = (i & 1) ? OFF_A1 : OFF_A0;
            const uint32_t boff = (i & 1) ? OFF_B1 : OFF_B0;
            #pragma unroll
            for (int k16 = 0; k16 < 4; k16++) {
                uint32_t af[2][4], bf[8][2];
                #pragma unroll
                for (int mt = 0; mt < 2; mt++) {
                    int row = wm * 32 + mt * 16 + arow_l;
                    int col = k16 * 32 + acolh;
                    ldsm4(af[mt], base + aoff +
                          (uint32_t)(row * 128 + (col ^ ((row & 7) * 16))));
                }
                #pragma unroll
                for (int p2 = 0; p2 < 4; p2++) {
                    uint32_t t4[4];
                    int row = wn * 64 + p2 * 16 + brow_l;
                    int col = k16 * 32 + bcolh;
                    ldsm4(t4, base + boff +
                          (uint32_t)(row * 128 + (col ^ ((row & 7) * 16))));
                    bf[2 * p2][0] = t4[0]; bf[2 * p2][1] = t4[1];
                    bf[2 * p2 + 1][0] = t4[2]; bf[2 * p2 + 1][1] = t4[3];
                }
                #pragma unroll
                for (int mt = 0; mt < 2; mt++)
                    #pragma unroll
                    for (int nt = 0; nt < 8; nt++)
                        mma_bf16(acc[mt][nt], af[mt], bf[nt]);
            }
            __syncthreads();
        }

        // epilogue: quantize exactly like reference, update best/second
        #pragma unroll
        for (int mt = 0; mt < 2; mt++)
            #pragma unroll
            for (int h = 0; h < 2; h++) {
                const int rr = mt * 2 + h;
                #pragma unroll
                for (int nt = 0; nt < 8; nt++)
                    #pragma unroll
                    for (int jj = 0; jj < 2; jj++) {
                        int col = wn * 64 + nt * 8 + qcol * 2 + jj;
                        float dot = acc[mt][nt][h * 2 + jj];
                        float d = __fadd_rn(__fadd_rn(znr[rr], sCN[col]),
                                            __fmul_rn(-2.0f, dot));
                        unsigned long long key =
                            ((unsigned long long)__float_as_uint(d) << 32) |
                            (unsigned)(kt * 128 + col);
                        if (key < bkey[rr]) {
                            secd[rr] = fminf(secd[rr],
                                __uint_as_float((uint32_t)(bkey[rr] >> 32)));
                            bkey[rr] = key;
                        } else {
                            secd[rr] = fminf(secd[rr], d);
                        }
                    }
            }
    }

    // quad (same-row lanes) reduction via shuffles
    #pragma unroll
    for (int rr = 0; rr < 4; rr++) {
        unsigned long long k = bkey[rr];
        float s = secd[rr];
        #pragma unroll
        for (int off = 1; off <= 2; off <<= 1) {
            unsigned long long ko = __shfl_xor_sync(0xffffffffu, k, off);
            float so = __shfl_xor_sync(0xffffffffu, s, off);
            unsigned long long kmin = (k < ko) ? k : ko;
            unsigned long long kmax = (k < ko) ? ko : k;
            s = fminf(fminf(s, so), __uint_as_float((uint32_t)(kmax >> 32)));
            k = kmin;
        }
        if (qcol == 0) {
            int row = wm * 32 + (rr >> 1) * 16 + (rr & 1) * 8 + qrow;
            redK[wn * 128 + row] = k;
            redS[wn * 128 + row] = s;
        }
    }
    __syncthreads();
    if (tid < 128) {
        unsigned long long k1 = redK[tid], k2 = redK[128 + tid];
        float s1 = redS[tid], s2 = redS[128 + tid];
        unsigned long long kb = (k1 < k2) ? k1 : k2;
        unsigned long long ko = (k1 < k2) ? k2 : k1;
        float bv = __uint_as_float((uint32_t)(kb >> 32));
        float sv = fminf(fminf(s1, s2), __uint_as_float((uint32_t)(ko >> 32)));
        int tok = tok0 + tid;
        g_idx[tok] = (int)(kb & 0xFFFFFFFFull);
        // flag only gap <= 2 ulp of the [256,512) binade (6.1e-5); >= 3 ulp is
        // provably decided identically to the reference (dot error << ulp/2).
        if (sv - bv < 6.2e-5f) {
            int p = atomicAdd(&g_namb, 1);
            g_amb[p] = tok;
            g_bkey[p] = 0xFFFFFFFFFFFFFFFFull;
        }
    }
}

// ---------------- kernel: exact fp32 rescue for ambiguous tokens ----------------
// Group of 32 tokens split across 4 blocks (256 codes each); results merged via
// global 64-bit atomicMin. Codebook operand read as float4 broadcast; identical
// ascending-c sequential FMA chain as before (bit-identical decisions).
#define RESCUE_SMEM ((64 * CDIM + CDIM * 32) * 4)   // 64KB tile + 32KB zsT
__global__ void __launch_bounds__(256, 2)
vq_rescue(const float* __restrict__ z, const float* __restrict__ cb) {
    extern __shared__ float rs[];
    float* tile = rs;                  // [64][256]
    float* zsT  = rs + 64 * CDIM;      // [256][32]
    __shared__ float zn_s[32];
    __shared__ int   tok_s[32];
    const int nA = g_namb;
    const int gi = blockIdx.x >> 2;          // token group
    const int qc = blockIdx.x & 3;           // code quarter
    const int base_tok = gi * 32;
    if (base_tok >= nA) return;
    const int ng = min(32, nA - base_tok);
    const int tid = threadIdx.x;
    const int lane = tid & 31;
    const int w = tid >> 5;

    if (tid < 32) {
        int tk = (tid < ng) ? g_amb[base_tok + tid] : g_amb[base_tok];
        tok_s[tid] = tk;
        zn_s[tid] = g_znorm[tk];
    }
    __syncthreads();
    for (int q = tid; q < CDIM * 32; q += 256) {
        int c = q >> 5, tl = q & 31;
        int tk = tok_s[tl];
        int b = tk >> 11, t = tk & 2047;
        zsT[c * 32 + tl] = z[((size_t)b * CDIM + c) * TLEN + t];
    }

    for (int ti = 0; ti < 4; ti++) {
        const int kb = qc * 256 + ti * 64;
        __syncthreads();
        {
            const float4* src = (const float4*)(cb + (size_t)kb * CDIM);
            float4* dst = (float4*)tile;
            for (int q = tid; q < 64 * CDIM / 4; q += 256)
                dst[q] = src[q];
        }
        __syncthreads();
        if (lane < ng) {
            float acc[8];
            #pragma unroll
            for (int j = 0; j < 8; j++) acc[j] = 0.f;
            const int cj0 = w * 8;
            for (int c0 = 0; c0 < CDIM; c0 += 8) {
                float zreg[8];
                #pragma unroll
                for (int cc = 0; cc < 8; cc++)
                    zreg[cc] = zsT[(c0 + cc) * 32 + lane];
                #pragma unroll
                for (int j = 0; j < 8; j++) {
                    const float4* cp4 = (const float4*)(tile + (cj0 + j) * CDIM + c0);
                    float4 p0 = cp4[0];
                    float4 p1 = cp4[1];
                    acc[j] = __fmaf_rn(zreg[0], p0.x, acc[j]);
                    acc[j] = __fmaf_rn(zreg[1], p0.y, acc[j]);
                    acc[j] = __fmaf_rn(zreg[2], p0.z, acc[j]);
                    acc[j] = __fmaf_rn(zreg[3], p0.w, acc[j]);
                    acc[j] = __fmaf_rn(zreg[4], p1.x, acc[j]);
                    acc[j] = __fmaf_rn(zreg[5], p1.y, acc[j]);
                    acc[j] = __fmaf_rn(zreg[6], p1.z, acc[j]);
                    acc[j] = __fmaf_rn(zreg[7], p1.w, acc[j]);
                }
            }
            unsigned long long kmin = 0xFFFFFFFFFFFFFFFFull;
            #pragma unroll
            for (int j = 0; j < 8; j++) {
                int kk = kb + cj0 + j;
                float d = __fadd_rn(__fadd_rn(zn_s[lane], g_cnorm[kk]),
                                    __fmul_rn(-2.0f, acc[j]));
                unsigned long long key =
                    ((unsigned long long)__float_as_uint(d) << 32) | (unsigned)kk;
                if (key < kmin) kmin = key;
            }
            atomicMin(&g_bkey[base_tok + lane], kmin);
        }
    }
}

// ---------------- kernel: rescue finalize (write winning indices) ----------------
__global__ void vq_rescue_fin() {
    int n = blockIdx.x * blockDim.x + threadIdx.x;
    if (n < g_namb)
        g_idx[g_amb[n]] = (int)(g_bkey[n] & 0xFFFFFFFFull);
}

// ---------------- kernel: z_q gather + loss partial ----------------
// Block = 32 tokens x full C. lane = token, warp strides c by 8 so every 32B
// codebook sector is fetched once into L1 and reused; z reads / zq writes are
// fully coalesced (contiguous in t).
__global__ void vq_zq_kernel(const float* __restrict__ z,
                             const float* __restrict__ cb,
                             float* __restrict__ zq_out) {
    const int blk = blockIdx.x;           // NTOK/32
    const int b = blk >> 6;
    const int t0 = (blk & 63) * 32;
    const int tid = threadIdx.x;
    const int lane = tid & 31;
    const int w = tid >> 5;
    __shared__ int ks[32];
    if (tid < 32) ks[tid] = g_idx[b * TLEN + t0 + tid];
    __syncthreads();

    const float* crow = cb + (size_t)ks[lane] * CDIM;
    const size_t zb = (size_t)b * CDIM * TLEN + t0 + lane;
    float s = 0.f;
    #pragma unroll 4
    for (int c = w; c < CDIM; c += 8) {
        float q  = __ldg(crow + c);
        float zv = z[zb + (size_t)c * TLEN];
        zq_out[zb + (size_t)c * TLEN] = q;
        float d = q - zv;
        s += d * d;
    }
    #pragma unroll
    for (int o = 16; o; o >>= 1) s += __shfl_down_sync(0xffffffffu, s, o);
    __shared__ float ws[8];
    if (lane == 0) ws[w] = s;
    __syncthreads();
    if (tid == 0) {
        float tot = 0.f;
        #pragma unroll
        for (int wv = 0; wv < 8; wv++) tot += ws[wv];
        atomicAdd(&g_sqsum, (double)tot);
    }
}

// ---------------- kernel: one-hot scatter + counts + index output ----------------
__global__ void vq_scatter_kernel(float* __restrict__ onehot,
                                  float* __restrict__ idx_out) {
    int n = blockIdx.x * blockDim.x + threadIdx.x;
    if (n >= NTOK) return;
    int k = g_idx[n];
    onehot[(size_t)n * KCODES + k] = 1.0f;
    atomicAdd(&g_counts[k], 1u);
    idx_out[n] = (float)k;
}

// ---------------- kernel: finalize loss + perplexity ----------------
__global__ void vq_finalize_kernel(float* __restrict__ loss_out,
                                   float* __restrict__ perp_out) {
    const int tid = threadIdx.x;
    double local = 0.0;
    for (int k = tid; k < KCODES; k += 256) {
        float p = (float)g_counts[k] * (1.0f / (float)NTOK);
        local += (double)(p * logf(p + 1e-10f));
    }
    __shared__ double sh[256];
    sh[tid] = local;
    __syncthreads();
    for (int o = 128; o; o >>= 1) {
        if (tid < o) sh[tid] += sh[tid + o];
        __syncthreads();
    }
    if (tid == 0) {
        perp_out[0] = expf(-(float)sh[0]);
        loss_out[0] = (1.0f + BETA) *
                      (float)(g_sqsum / (double)((size_t)NTOK * CDIM));
    }
}

// ---------------- launch ----------------
extern "C" void kernel_launch(void* const* d_in, const int* in_sizes, int n_in,
                              void* d_out, int out_size) {
    const float* z  = (const float*)d_in[0];
    const float* cb = (const float*)d_in[1];
    float* out = (float*)d_out;

    const size_t n_zq = (size_t)BATCH * CDIM * TLEN;   // 16777216
    float* loss_out = out;
    float* zq_out   = out + 1;
    float* perp_out = out + 1 + n_zq;
    float* onehot   = perp_out + 1;
    float* idx_out  = onehot + (size_t)NTOK * KCODES;

    cudaFuncSetAttribute(vq_argmin_mma, cudaFuncAttributeMaxDynamicSharedMemorySize, ARGMIN_SMEM);
    cudaFuncSetAttribute(vq_rescue,     cudaFuncAttributeMaxDynamicSharedMemorySize, RESCUE_SMEM);

    cudaMemsetAsync(onehot, 0, (size_t)NTOK * KCODES * sizeof(float), 0);

    vq_split_cb<<<KCODES, 256>>>(cb);
    vq_split_z<<<NTOK / 32, 256>>>(z);
    vq_argmin_mma<<<NTOK / 128, 256, ARGMIN_SMEM>>>();
    vq_rescue<<<8192, 256, RESCUE_SMEM>>>(z, cb);
    vq_rescue_fin<<<NTOK / 256, 256>>>();
    vq_zq_kernel<<<NTOK / 32, 256>>>(z, cb, zq_out);
    vq_scatter_kernel<<<NTOK / 256, 256>>>(onehot, idx_out);
    vq_finalize_kernel<<<1, 256>>>(loss_out, perp_out);
}